// round 5
// baseline (speedup 1.0000x reference)
#include <cuda_runtime.h>
#include <cstdint>

__device__ double g_partials[4096];
__device__ unsigned int g_done_count = 0;

__global__ void __launch_bounds__(1024, 1)
center_loss_fused(const float* __restrict__ x,
                  const float* __restrict__ centers,
                  const int* __restrict__ labels_raw,
                  float* __restrict__ out,
                  int B, int D, int C) {
    const int lane = threadIdx.x & 31;
    const int warp_in_blk = threadIdx.x >> 5;
    const int warps_per_blk = blockDim.x >> 5;
    const int gwarp = blockIdx.x * warps_per_blk + warp_in_blk;
    const int nwarps = gridDim.x * warps_per_blk;
    const int n4 = D >> 2;

    double local = 0.0;

    if (n4 == 128) {
        for (int row = gwarp; row < B; row += nwarps) {
            // ---- phase 0: issue EVERYTHING independent back-to-back ----
            // dtype probe word (per-warp, no barrier; L1 hit after warp 0)
            int nsample = B < 32 ? B : 32;
            int probe = (lane < nsample) ? labels_raw[2 * lane + 1] : 0;
            // speculative label loads for both dtypes
            int cand32 = labels_raw[row];
            long long cand64 = ((const long long*)labels_raw)[row];
            // all 4 x-row LDG.128
            const float4* __restrict__ xr =
                reinterpret_cast<const float4*>(x + (size_t)row * D);
            float4 a0 = xr[lane];
            float4 a1 = xr[lane + 32];
            float4 a2 = xr[lane + 64];
            float4 a3 = xr[lane + 96];

            // ---- phase 1: resolve label while x data streams in ----
            unsigned any = __ballot_sync(0xFFFFFFFFu, probe != 0);
            long long li = (any == 0) ? cand64 : (long long)cand32;
            if (li < 0) li = 0;
            if (li >= C) li = C - 1;

            // ---- phase 2: issue all 4 center LDG.128 back-to-back ----
            const float4* __restrict__ cr =
                reinterpret_cast<const float4*>(centers + (size_t)li * D);
            float4 b0 = cr[lane];
            float4 b1 = cr[lane + 32];
            float4 b2 = cr[lane + 64];
            float4 b3 = cr[lane + 96];

            // x-norm overlaps the center round-trip
            float xsq = 0.f;
            xsq = fmaf(a0.x, a0.x, fmaf(a0.y, a0.y, fmaf(a0.z, a0.z, fmaf(a0.w, a0.w, xsq))));
            xsq = fmaf(a1.x, a1.x, fmaf(a1.y, a1.y, fmaf(a1.z, a1.z, fmaf(a1.w, a1.w, xsq))));
            xsq = fmaf(a2.x, a2.x, fmaf(a2.y, a2.y, fmaf(a2.z, a2.z, fmaf(a2.w, a2.w, xsq))));
            xsq = fmaf(a3.x, a3.x, fmaf(a3.y, a3.y, fmaf(a3.z, a3.z, fmaf(a3.w, a3.w, xsq))));

            // ---- phase 3: dot + center norm ----
            float dot = 0.f, csq = 0.f;
            dot = fmaf(a0.x, b0.x, fmaf(a0.y, b0.y, fmaf(a0.z, b0.z, fmaf(a0.w, b0.w, dot))));
            csq = fmaf(b0.x, b0.x, fmaf(b0.y, b0.y, fmaf(b0.z, b0.z, fmaf(b0.w, b0.w, csq))));
            dot = fmaf(a1.x, b1.x, fmaf(a1.y, b1.y, fmaf(a1.z, b1.z, fmaf(a1.w, b1.w, dot))));
            csq = fmaf(b1.x, b1.x, fmaf(b1.y, b1.y, fmaf(b1.z, b1.z, fmaf(b1.w, b1.w, csq))));
            dot = fmaf(a2.x, b2.x, fmaf(a2.y, b2.y, fmaf(a2.z, b2.z, fmaf(a2.w, b2.w, dot))));
            csq = fmaf(b2.x, b2.x, fmaf(b2.y, b2.y, fmaf(b2.z, b2.z, fmaf(b2.w, b2.w, csq))));
            dot = fmaf(a3.x, b3.x, fmaf(a3.y, b3.y, fmaf(a3.z, b3.z, fmaf(a3.w, b3.w, dot))));
            csq = fmaf(b3.x, b3.x, fmaf(b3.y, b3.y, fmaf(b3.z, b3.z, fmaf(b3.w, b3.w, csq))));

            #pragma unroll
            for (int o = 16; o > 0; o >>= 1) {
                dot += __shfl_down_sync(0xFFFFFFFFu, dot, o);
                xsq += __shfl_down_sync(0xFFFFFFFFu, xsq, o);
                csq += __shfl_down_sync(0xFFFFFFFFu, csq, o);
            }
            if (lane == 0) {
                float v = 0.5f * (xsq + csq) + 0.3f * dot;
                v = fminf(fmaxf(v, 1e-12f), 1e12f);
                local += (double)v;
            }
        }
    } else {
        // generic fallback (labels dtype probed per-warp, same trick)
        int nsample = B < 32 ? B : 32;
        int probe = (lane < nsample) ? labels_raw[2 * lane + 1] : 0;
        unsigned any = __ballot_sync(0xFFFFFFFFu, probe != 0);
        const int is64 = (any == 0);
        for (int row = gwarp; row < B; row += nwarps) {
            long long li = is64 ? ((const long long*)labels_raw)[row]
                                : (long long)labels_raw[row];
            if (li < 0) li = 0;
            if (li >= C) li = C - 1;
            const float4* xr = reinterpret_cast<const float4*>(x + (size_t)row * D);
            const float4* cr = reinterpret_cast<const float4*>(centers + (size_t)li * D);
            float dot = 0.f, xsq = 0.f, csq = 0.f;
            for (int i = lane; i < n4; i += 32) {
                float4 a = xr[i];
                float4 b = cr[i];
                dot = fmaf(a.x, b.x, fmaf(a.y, b.y, fmaf(a.z, b.z, fmaf(a.w, b.w, dot))));
                xsq = fmaf(a.x, a.x, fmaf(a.y, a.y, fmaf(a.z, a.z, fmaf(a.w, a.w, xsq))));
                csq = fmaf(b.x, b.x, fmaf(b.y, b.y, fmaf(b.z, b.z, fmaf(b.w, b.w, csq))));
            }
            #pragma unroll
            for (int o = 16; o > 0; o >>= 1) {
                dot += __shfl_down_sync(0xFFFFFFFFu, dot, o);
                xsq += __shfl_down_sync(0xFFFFFFFFu, xsq, o);
                csq += __shfl_down_sync(0xFFFFFFFFu, csq, o);
            }
            if (lane == 0) {
                float v = 0.5f * (xsq + csq) + 0.3f * dot;
                v = fminf(fmaxf(v, 1e-12f), 1e12f);
                local += (double)v;
            }
        }
    }

    // ---- block partial (deterministic order) ----
    __shared__ double sdata[32];
    if (lane == 0) sdata[warp_in_blk] = local;
    __syncthreads();
    if (warp_in_blk == 0) {
        double s = (lane < warps_per_blk) ? sdata[lane] : 0.0;
        // deterministic tree over 32 lanes via shuffle on doubles
        #pragma unroll
        for (int o = 16; o > 0; o >>= 1)
            s += __shfl_down_sync(0xFFFFFFFFu, s, o);
        if (lane == 0) g_partials[blockIdx.x] = s;
    }

    // ---- last-block-done final reduction ----
    __shared__ bool s_last;
    __threadfence();
    if (threadIdx.x == 0) {
        unsigned int prev = atomicAdd(&g_done_count, 1u);
        s_last = (prev == gridDim.x - 1);
    }
    __syncthreads();
    if (s_last && warp_in_blk == 0) {
        // one warp reduces gridDim.x partials (<= 4096), deterministic order
        double s = 0.0;
        for (int i = lane; i < (int)gridDim.x; i += 32)
            s += g_partials[i];
        #pragma unroll
        for (int o = 16; o > 0; o >>= 1)
            s += __shfl_down_sync(0xFFFFFFFFu, s, o);
        if (lane == 0) {
            double masked_zeros = ((double)B * (double)C - (double)B) * 1e-12;
            out[0] = (float)((s + masked_zeros) / (double)B);
            g_done_count = 0;  // reset for graph replay
        }
    }
}

extern "C" void kernel_launch(void* const* d_in, const int* in_sizes, int n_in,
                              void* d_out, int out_size) {
    const float* x = (const float*)d_in[0];
    const float* centers = (const float*)d_in[1];
    const int* labels = (const int*)d_in[2];
    float* out = (float*)d_out;

    const int B = in_sizes[2];
    const int D = in_sizes[0] / B;
    const int C = in_sizes[1] / D;

    const int threads = 1024;   // 32 warps/block, 1 CTA/SM
    const int warps_per_blk = threads / 32;
    int blocks = (B + warps_per_blk - 1) / warps_per_blk;  // B=4096 -> 128 (< 148 SMs, oe=1)
    if (blocks > 4096) blocks = 4096;
    if (blocks < 1) blocks = 1;

    center_loss_fused<<<blocks, threads>>>(x, centers, labels, out, B, D, C);
}

// round 6
// speedup vs baseline: 1.0239x; 1.0239x over previous
#include <cuda_runtime.h>
#include <cstdint>

__device__ double g_partials[4096];
__device__ unsigned int g_done_count = 0;

__global__ void __launch_bounds__(1024, 1)
center_loss_fused(const float* __restrict__ x,
                  const float* __restrict__ centers,
                  const int* __restrict__ labels_raw,
                  float* __restrict__ out,
                  int B, int D, int C) {
    const int lane = threadIdx.x & 31;
    const int warp_in_blk = threadIdx.x >> 5;
    const int warps_per_blk = blockDim.x >> 5;
    const int gwarp = blockIdx.x * warps_per_blk + warp_in_blk;
    const int nwarps = gridDim.x * warps_per_blk;
    const int n4 = D >> 2;

    double local = 0.0;

    if (n4 == 128) {
        for (int row = gwarp; row < B; row += nwarps) {
            // phase 0: every independent load issued back-to-back
            int nsample = B < 32 ? B : 32;
            int probe = (lane < nsample) ? labels_raw[2 * lane + 1] : 0;
            int cand32 = labels_raw[row];
            long long cand64 = ((const long long*)labels_raw)[row];
            const float4* __restrict__ xr =
                reinterpret_cast<const float4*>(x + (size_t)row * D);
            float4 a0 = xr[lane];
            float4 a1 = xr[lane + 32];
            float4 a2 = xr[lane + 64];
            float4 a3 = xr[lane + 96];

            // phase 1: resolve label dtype while x streams in
            unsigned any = __ballot_sync(0xFFFFFFFFu, probe != 0);
            long long li = (any == 0) ? cand64 : (long long)cand32;
            if (li < 0) li = 0;
            if (li >= C) li = C - 1;

            // phase 2: all center loads back-to-back
            const float4* __restrict__ cr =
                reinterpret_cast<const float4*>(centers + (size_t)li * D);
            float4 b0 = cr[lane];
            float4 b1 = cr[lane + 32];
            float4 b2 = cr[lane + 64];
            float4 b3 = cr[lane + 96];

            // x-norm overlaps the center round-trip
            float xsq = 0.f;
            xsq = fmaf(a0.x, a0.x, fmaf(a0.y, a0.y, fmaf(a0.z, a0.z, fmaf(a0.w, a0.w, xsq))));
            xsq = fmaf(a1.x, a1.x, fmaf(a1.y, a1.y, fmaf(a1.z, a1.z, fmaf(a1.w, a1.w, xsq))));
            xsq = fmaf(a2.x, a2.x, fmaf(a2.y, a2.y, fmaf(a2.z, a2.z, fmaf(a2.w, a2.w, xsq))));
            xsq = fmaf(a3.x, a3.x, fmaf(a3.y, a3.y, fmaf(a3.z, a3.z, fmaf(a3.w, a3.w, xsq))));

            // phase 3: dot + center norm (two independent chains)
            float dot = 0.f, csq = 0.f;
            dot = fmaf(a0.x, b0.x, fmaf(a0.y, b0.y, fmaf(a0.z, b0.z, fmaf(a0.w, b0.w, dot))));
            csq = fmaf(b0.x, b0.x, fmaf(b0.y, b0.y, fmaf(b0.z, b0.z, fmaf(b0.w, b0.w, csq))));
            dot = fmaf(a1.x, b1.x, fmaf(a1.y, b1.y, fmaf(a1.z, b1.z, fmaf(a1.w, b1.w, dot))));
            csq = fmaf(b1.x, b1.x, fmaf(b1.y, b1.y, fmaf(b1.z, b1.z, fmaf(b1.w, b1.w, csq))));
            dot = fmaf(a2.x, b2.x, fmaf(a2.y, b2.y, fmaf(a2.z, b2.z, fmaf(a2.w, b2.w, dot))));
            csq = fmaf(b2.x, b2.x, fmaf(b2.y, b2.y, fmaf(b2.z, b2.z, fmaf(b2.w, b2.w, csq))));
            dot = fmaf(a3.x, b3.x, fmaf(a3.y, b3.y, fmaf(a3.z, b3.z, fmaf(a3.w, b3.w, dot))));
            csq = fmaf(b3.x, b3.x, fmaf(b3.y, b3.y, fmaf(b3.z, b3.z, fmaf(b3.w, b3.w, csq))));

            // combine per-lane FIRST (linear), then ONE shuffle chain
            float v = fmaf(0.3f, dot, 0.5f * (xsq + csq));
            #pragma unroll
            for (int o = 16; o > 0; o >>= 1)
                v += __shfl_down_sync(0xFFFFFFFFu, v, o);

            if (lane == 0) {
                v = fminf(fmaxf(v, 1e-12f), 1e12f);
                local += (double)v;
            }
        }
    } else {
        int nsample = B < 32 ? B : 32;
        int probe = (lane < nsample) ? labels_raw[2 * lane + 1] : 0;
        unsigned any = __ballot_sync(0xFFFFFFFFu, probe != 0);
        const int is64 = (any == 0);
        for (int row = gwarp; row < B; row += nwarps) {
            long long li = is64 ? ((const long long*)labels_raw)[row]
                                : (long long)labels_raw[row];
            if (li < 0) li = 0;
            if (li >= C) li = C - 1;
            const float4* xr = reinterpret_cast<const float4*>(x + (size_t)row * D);
            const float4* cr = reinterpret_cast<const float4*>(centers + (size_t)li * D);
            float dot = 0.f, xsq = 0.f, csq = 0.f;
            for (int i = lane; i < n4; i += 32) {
                float4 a = xr[i];
                float4 b = cr[i];
                dot = fmaf(a.x, b.x, fmaf(a.y, b.y, fmaf(a.z, b.z, fmaf(a.w, b.w, dot))));
                xsq = fmaf(a.x, a.x, fmaf(a.y, a.y, fmaf(a.z, a.z, fmaf(a.w, a.w, xsq))));
                csq = fmaf(b.x, b.x, fmaf(b.y, b.y, fmaf(b.z, b.z, fmaf(b.w, b.w, csq))));
            }
            float v = fmaf(0.3f, dot, 0.5f * (xsq + csq));
            #pragma unroll
            for (int o = 16; o > 0; o >>= 1)
                v += __shfl_down_sync(0xFFFFFFFFu, v, o);
            if (lane == 0) {
                v = fminf(fmaxf(v, 1e-12f), 1e12f);
                local += (double)v;
            }
        }
    }

    // ---- block partial: warp0 shuffle-reduce over per-warp doubles ----
    __shared__ double sdata[32];
    if (lane == 0) sdata[warp_in_blk] = local;
    __syncthreads();
    if (warp_in_blk == 0) {
        double s = (lane < warps_per_blk) ? sdata[lane] : 0.0;
        #pragma unroll
        for (int o = 16; o > 0; o >>= 1)
            s += __shfl_down_sync(0xFFFFFFFFu, s, o);
        if (lane == 0) g_partials[blockIdx.x] = s;
    }

    // ---- last-block-done final reduction ----
    __shared__ bool s_last;
    __threadfence();
    if (threadIdx.x == 0) {
        unsigned int prev = atomicAdd(&g_done_count, 1u);
        s_last = (prev == gridDim.x - 1);
    }
    __syncthreads();
    if (s_last && warp_in_blk == 0) {
        double s = 0.0;
        for (int i = lane; i < (int)gridDim.x; i += 32)
            s += g_partials[i];
        #pragma unroll
        for (int o = 16; o > 0; o >>= 1)
            s += __shfl_down_sync(0xFFFFFFFFu, s, o);
        if (lane == 0) {
            double masked_zeros = ((double)B * (double)C - (double)B) * 1e-12;
            out[0] = (float)((s + masked_zeros) / (double)B);
            g_done_count = 0;  // reset for graph replay
        }
    }
}

extern "C" void kernel_launch(void* const* d_in, const int* in_sizes, int n_in,
                              void* d_out, int out_size) {
    const float* x = (const float*)d_in[0];
    const float* centers = (const float*)d_in[1];
    const int* labels = (const int*)d_in[2];
    float* out = (float*)d_out;

    const int B = in_sizes[2];
    const int D = in_sizes[0] / B;
    const int C = in_sizes[1] / D;

    const int threads = 1024;   // 32 warps/block, 1 CTA/SM, oe=1 balanced
    const int warps_per_blk = threads / 32;
    int blocks = (B + warps_per_blk - 1) / warps_per_blk;   // B=4096 -> 128
    if (blocks > 4096) blocks = 4096;
    if (blocks < 1) blocks = 1;

    center_loss_fused<<<blocks, threads>>>(x, centers, labels, out, B, D, C);
}